// round 5
// baseline (speedup 1.0000x reference)
#include <cuda_runtime.h>
#include <cuda_bf16.h>
#include <cstdint>

#define NUM_CLASSES 100000
#define EMBED 512
#define BATCH_N 4096
#define LAMBDA_C 0.01f
#define ALPHA_C 0.1f

#define NCS ((size_t)NUM_CLASSES * EMBED)        // 51,200,000 elements
#define NQ  ((NCS - 4) / 4)                      // 12,799,999 aligned dst chunks

// Per-class linked lists of sample indices (scratch; rebuilt every call).
__device__ int g_head[NUM_CLASSES];
__device__ int g_next[BATCH_N];

// build per-class chains (duplicates accumulate via the chain) + zero loss
__global__ __launch_bounds__(256)
void build_kernel(const int* __restrict__ y, float* __restrict__ loss) {
    int i = blockIdx.x * blockDim.x + threadIdx.x;
    if (i == 0) *loss = 0.0f;
    if (i < BATCH_N) {
        int c = y[i];
        int old = atomicExch(&g_head[c], i);
        g_next[i] = old;
    }
}

// Pure streaming copy centers -> new_centers (= out+1, 4B misaligned).
// Chunking shifted so STORES are 16B-aligned: chunk q covers dst elements
// [3+4q .. 6+4q] = {src[3+4q], src[4+4q..6+4q]}. Each thread does one aligned
// LDG.128 of src float4 (q+1); the straddler src[3+4q] comes from the
// previous lane via shfl_up (lane 0: one scalar load).
__global__ __launch_bounds__(256)
void copy_shifted_kernel(const float* __restrict__ src,
                         float* __restrict__ dst /* = new_centers */) {
    const size_t q = (size_t)blockIdx.x * blockDim.x + threadIdx.x;
    const int lane = threadIdx.x & 31;

    // clamped load so the one overhang thread stays in bounds
    size_t jload = q + 1;
    if (jload > NCS / 4 - 1) jload = NCS / 4 - 1;
    float4 a = __ldcs(reinterpret_cast<const float4*>(src) + jload);

    float prev_w = __shfl_up_sync(0xFFFFFFFFu, a.w, 1);
    if (lane == 0 && q < NQ)
        prev_w = __ldcs(src + 4 * q + 3);

    if (q < NQ) {
        float4 v = make_float4(prev_w, a.x, a.y, a.z);
        __stcs(reinterpret_cast<float4*>(dst + 3 + 4 * q), v);
    }

    // head + tail scalars
    if (q == 0) {
        dst[0] = src[0];
        dst[1] = src[1];
        dst[2] = src[2];
        dst[NCS - 1] = src[NCS - 1];
    }
}

// Fixup: one block per sample. Every block adds its own sample's loss term.
// Only the chain-head block recomputes the touched row and overwrites it.
__global__ __launch_bounds__(128)
void fixup_kernel(const int* __restrict__ y,
                  const float4* __restrict__ batch4,
                  const float4* __restrict__ centers4,
                  float* __restrict__ dst,
                  float* __restrict__ loss) {
    const int i = blockIdx.x;
    const int t = threadIdx.x;          // 0..127, one float4 each
    const int c = y[i];

    float4 c4 = centers4[(size_t)c * (EMBED / 4) + t];

    // own loss term
    {
        float4 b4 = batch4[(size_t)i * (EMBED / 4) + t];
        float dx = b4.x - c4.x, dy = b4.y - c4.y;
        float dz = b4.z - c4.z, dw = b4.w - c4.w;
        float ls = dx * dx + dy * dy + dz * dz + dw * dw;
        #pragma unroll
        for (int off = 16; off > 0; off >>= 1)
            ls += __shfl_xor_sync(0xFFFFFFFFu, ls, off);
        __shared__ float wsum[4];
        if ((t & 31) == 0) wsum[t >> 5] = ls;
        __syncthreads();
        if (t == 0) {
            float tot = wsum[0] + wsum[1] + wsum[2] + wsum[3];
            atomicAdd(loss, tot * (LAMBDA_C / (float)BATCH_N));
        }
    }

    // chain head writes the updated row (single writer per class)
    if (g_head[c] == i) {
        float ax = 0.f, ay = 0.f, az = 0.f, aw = 0.f;
        int s = i;
        while (s >= 0) {
            float4 b4 = batch4[(size_t)s * (EMBED / 4) + t];
            ax += b4.x - c4.x;
            ay += b4.y - c4.y;
            az += b4.z - c4.z;
            aw += b4.w - c4.w;
            s = g_next[s];
        }
        float* d = dst + (size_t)c * EMBED + t * 4;
        d[0] = c4.x + ALPHA_C * ax;
        d[1] = c4.y + ALPHA_C * ay;
        d[2] = c4.z + ALPHA_C * az;
        d[3] = c4.w + ALPHA_C * aw;
    }
}

extern "C" void kernel_launch(void* const* d_in, const int* in_sizes, int n_in,
                              void* d_out, int out_size) {
    const int*   y       = (const int*)d_in[0];
    const float* batch   = (const float*)d_in[1];
    const float* centers = (const float*)d_in[2];

    float* out = (float*)d_out;

    float* loss_ptr;
    float* new_centers;
    if (out_size == (int)(NCS + 1)) {
        loss_ptr = out;
        new_centers = out + 1;
    } else {
        new_centers = out;
        loss_ptr = out + NCS;
    }

    // 1) reset heads to -1 (0xFF bytes == -1 as int)
    void* head_ptr = nullptr;
    cudaGetSymbolAddress(&head_ptr, g_head);
    cudaMemsetAsync(head_ptr, 0xFF, NUM_CLASSES * sizeof(int), 0);

    // 2) build chains + zero loss
    build_kernel<<<(BATCH_N + 255) / 256, 256>>>(y, loss_ptr);

    // 3) bulk aligned copy (12.8M threads: 50000 blocks x 256)
    const unsigned blocks = (unsigned)((NQ + 256) / 256);   // covers q in [0, NQ]
    copy_shifted_kernel<<<blocks, 256>>>(centers, new_centers);

    // 4) sparse fixup of touched rows + loss
    fixup_kernel<<<BATCH_N, 128>>>(y,
        reinterpret_cast<const float4*>(batch),
        reinterpret_cast<const float4*>(centers),
        new_centers, loss_ptr);
}

// round 6
// speedup vs baseline: 1.0860x; 1.0860x over previous
#include <cuda_runtime.h>
#include <cuda_bf16.h>
#include <cstdint>

#define NUM_CLASSES 100000
#define EMBED 512
#define BATCH_N 4096
#define LAMBDA_C 0.01f
#define ALPHA_C 0.1f

// Per-class linked lists of sample indices (scratch; rebuilt every call).
__device__ int g_head[NUM_CLASSES];
__device__ int g_next[BATCH_N];

// build per-class chains (duplicates accumulate via the chain) + zero loss
__global__ __launch_bounds__(256)
void build_kernel(const int* __restrict__ y, float* __restrict__ loss) {
    int i = blockIdx.x * blockDim.x + threadIdx.x;
    if (i == 0) *loss = 0.0f;
    if (i < BATCH_N) {
        int c = y[i];
        int old = atomicExch(&g_head[c], i);
        g_next[i] = old;
    }
}

// Fused copy + sparse overwrite, one streaming pass over all centers.
// 256 threads = 2 class rows per block; 128 threads / row, one float4 each.
// KEY: the plain copy store depends ONLY on the c4 load (same dependency
// structure as a pure copy); the rare updated-row overwrite happens after,
// program-ordered on the same thread/addresses.
__global__ __launch_bounds__(256)
void fused_copy_apply_kernel(const float4* __restrict__ centers4,
                             const float4* __restrict__ batch4,
                             float* __restrict__ dst,
                             float* __restrict__ loss) {
    const int row = blockIdx.x * 2 + (threadIdx.x >> 7);
    const int t   = threadIdx.x & 127;          // float4 index within row

    const int h = g_head[row];                  // independent broadcast load
    float4 c4 = __ldcs(centers4 + (size_t)row * (EMBED / 4) + t);

    // unconditional copy: issues as soon as c4 lands (hot path = pure copy)
    float* d = dst + (size_t)row * EMBED + t * 4;   // dst misaligned by 4B
    __stcs(d + 0, c4.x);
    __stcs(d + 1, c4.y);
    __stcs(d + 2, c4.z);
    __stcs(d + 3, c4.w);

    // rare path: row was touched by >=1 sample -> overwrite with update
    if (h >= 0) {
        float ax = 0.f, ay = 0.f, az = 0.f, aw = 0.f, ls = 0.f;
        int s = h;
        while (s >= 0) {
            float4 b4 = batch4[(size_t)s * (EMBED / 4) + t];
            float dx = b4.x - c4.x;
            float dy = b4.y - c4.y;
            float dz = b4.z - c4.z;
            float dw = b4.w - c4.w;
            ax += dx; ay += dy; az += dz; aw += dw;
            ls += dx * dx + dy * dy + dz * dz + dw * dw;
            s = g_next[s];
        }
        // same-thread same-address stores are program-ordered: final wins
        d[0] = c4.x + ALPHA_C * ax;
        d[1] = c4.y + ALPHA_C * ay;
        d[2] = c4.z + ALPHA_C * az;
        d[3] = c4.w + ALPHA_C * aw;

        // loss reduce (uniform per warp: all 128 threads of the row branch)
        #pragma unroll
        for (int off = 16; off > 0; off >>= 1)
            ls += __shfl_xor_sync(0xFFFFFFFFu, ls, off);
        if ((t & 31) == 0)
            atomicAdd(loss, ls * (LAMBDA_C / (float)BATCH_N));
    }
}

extern "C" void kernel_launch(void* const* d_in, const int* in_sizes, int n_in,
                              void* d_out, int out_size) {
    const int*   y       = (const int*)d_in[0];
    const float* batch   = (const float*)d_in[1];
    const float* centers = (const float*)d_in[2];

    float* out = (float*)d_out;
    const size_t ncs = (size_t)NUM_CLASSES * EMBED;

    float* loss_ptr;
    float* new_centers;
    if (out_size == (int)(ncs + 1)) {
        loss_ptr = out;
        new_centers = out + 1;
    } else {
        new_centers = out;
        loss_ptr = out + ncs;
    }

    // 1) reset heads to -1 (0xFF bytes == -1 as int)
    void* head_ptr = nullptr;
    cudaGetSymbolAddress(&head_ptr, g_head);
    cudaMemsetAsync(head_ptr, 0xFF, NUM_CLASSES * sizeof(int), 0);

    // 2) build chains + zero loss
    build_kernel<<<(BATCH_N + 255) / 256, 256>>>(y, loss_ptr);

    // 3) fused streaming copy + sparse overwrite
    fused_copy_apply_kernel<<<NUM_CLASSES / 2, 256>>>(
        reinterpret_cast<const float4*>(centers),
        reinterpret_cast<const float4*>(batch),
        new_centers, loss_ptr);
}